// round 13
// baseline (speedup 1.0000x reference)
#include <cuda_runtime.h>
#include <cuda_bf16.h>
#include <cstdint>
#include <math.h>

// Problem constants
#define BATCH 16
#define SEQ   2048
#define NLAYER 4
#define BNTOT (BATCH*SEQ)          // 32768
#define LSP   393728               // packed per-layer weight stride (floats)

// ---------------- scratch (device globals) ----------------------------------
__device__ float g_V [(size_t)BNTOT*256];        // LN output (raw fp32)
__device__ float g_Bu[(size_t)BNTOT*512];        // [Bu_re | Bu_im]
__device__ float g_X [(size_t)BNTOT*512];        // scan out: x_right only (raw fp32)
__device__ float g_Y [(size_t)2*BNTOT*256];      // gelu(y) raw (right rows 0.., left rows BN..)
__device__ float g_U [(size_t)2*BNTOT*256];      // right_u rows 0.., left_u rows BN..
__device__ float g_Wh[(size_t)NLAYER*LSP + 65536]; // packed weights hi (+embed)
__device__ float g_Wl[(size_t)NLAYER*LSP + 65536]; // packed weights lo

// ---------------- helpers ----------------------------------------------------
static __device__ __forceinline__ uint32_t smem_u32(const void* p) {
    uint32_t a;
    asm("{ .reg .u64 t; cvta.to.shared.u64 t, %1; cvt.u32.u64 %0, t; }" : "=r"(a) : "l"(p));
    return a;
}
static __device__ __forceinline__ void cp16(uint32_t dst, const void* src) {
    asm volatile("cp.async.cg.shared.global [%0], [%1], 16;" :: "r"(dst), "l"(src));
}
#define CP_COMMIT() asm volatile("cp.async.commit_group;" ::: "memory")
#define CP_WAIT1()  asm volatile("cp.async.wait_group 1;" ::: "memory")
#define CP_WAIT0()  asm volatile("cp.async.wait_group 0;" ::: "memory")

static __device__ __forceinline__ uint32_t to_tf32(float x) {
    uint32_t r;
    asm("cvt.rna.tf32.f32 %0, %1;" : "=r"(r) : "f"(x));
    return r;
}
// split x into tf32-rounded hi + lo, stored as fp32 words
static __device__ __forceinline__ void fsplit(float x, float& hi, float& lo) {
    hi = __uint_as_float(to_tf32(x));
    lo = __uint_as_float(to_tf32(x - hi));
}
static __device__ __forceinline__ void mma8(float* c, const uint32_t* a, const uint32_t* b) {
    asm volatile("mma.sync.aligned.m16n8k8.row.col.f32.tf32.tf32.f32 "
                 "{%0,%1,%2,%3}, {%4,%5,%6,%7}, {%8,%9}, {%0,%1,%2,%3};"
                 : "+f"(c[0]), "+f"(c[1]), "+f"(c[2]), "+f"(c[3])
                 : "r"(a[0]), "r"(a[1]), "r"(a[2]), "r"(a[3]), "r"(b[0]), "r"(b[1]));
}
static __device__ __forceinline__ void ldsm4(uint32_t* r, uint32_t addr) {
    asm volatile("ldmatrix.sync.aligned.m8n8.x4.shared.b16 {%0,%1,%2,%3}, [%4];"
                 : "=r"(r[0]), "=r"(r[1]), "=r"(r[2]), "=r"(r[3]) : "r"(addr));
}

// Taylor sin/cos for |t| <= ~1.3 (scan phase is bounded by |Lam_im|*dt*delta).
// Truncation error <= 3e-9 -- library-accuracy, unlike __sincosf (R8 failure).
static __device__ __forceinline__ float sin_poly(float t) {
    float t2 = t * t;
    float p = -2.5052108e-8f;
    p = fmaf(p, t2,  2.7557319e-6f);
    p = fmaf(p, t2, -1.9841270e-4f);
    p = fmaf(p, t2,  8.3333333e-3f);
    p = fmaf(p, t2, -0.16666667f);
    p = fmaf(p, t2,  1.0f);
    return t * p;
}
static __device__ __forceinline__ float cos_poly(float t) {
    float t2 = t * t;
    float p = 2.0876757e-9f;
    p = fmaf(p, t2, -2.7557319e-7f);
    p = fmaf(p, t2,  2.4801587e-5f);
    p = fmaf(p, t2, -1.3888889e-3f);
    p = fmaf(p, t2,  4.1666667e-2f);
    p = fmaf(p, t2, -0.5f);
    p = fmaf(p, t2,  1.0f);
    return p;
}

// ---------------- 3xTF32 mma.sync GEMM ---------------------------------------
// C(128x128 per CTA) = A(M x K, raw fp32) @ Bt(N x K, pre-split hi/lo)^T
// A is split hi/lo IN THE LOADER (ld.global.v4 -> fsplit -> st.shared).
// If by >= byHalf, A tile = A[by-byHalf] - Asub[by-byHalf] (x_left = x_right - Bu).
// 8 warps (2m x 4n), warp tile 64x32, BK=32, 2-stage pipeline (B via cp.async).
// Epilogue modes:
//  0: +bias, dual store to C and C2 (embed -> right_u/left_u)
//  1: plain store, row stride ldc (Bu)
//  2: gelu, raw store (g), stride 256
//  3: interleaved GLU pairs: C[r][gc/2] += (t1+b1)*sigmoid(t2+b2)
#define BKK   32
#define PADF  36                         // floats per smem row (144B, 16B-aligned)
#define PLANE (128*PADF)                 // one operand plane (floats)
#define STGF  (4*PLANE)                  // stage floats (Ah,Al,Bh,Bl)
#define GSMEM (2*STGF*4)                 // 147456 bytes

__global__ __launch_bounds__(256, 1) void gemm_mma(
    const float* __restrict__ A, const float* __restrict__ Asub,
    const float* __restrict__ Bhi, const float* __restrict__ Blo,
    const float* __restrict__ bias, float* __restrict__ C, float* __restrict__ C2,
    int ldc, int K, int mode, int byHalf)
{
    extern __shared__ float sm[];
    uint32_t sb = smem_u32(sm);
    int tid = threadIdx.x;
    int warp = tid >> 5, lane = tid & 31;
    int wm = warp & 1, wn = warp >> 1;
    int bx = blockIdx.x, by = blockIdx.y;

    const float* Ab;
    const float* As = nullptr;
    if (by >= byHalf) {
        Ab = A    + (size_t)(by - byHalf) * 128 * K;
        As = Asub + (size_t)(by - byHalf) * 128 * K;
    } else {
        Ab = A + (size_t)by * 128 * K;
    }
    const float* Bh = Bhi + (size_t)bx * 128 * K;
    const float* Bl = Blo + (size_t)bx * 128 * K;
    int NT = K / BKK;

    int lrow = tid >> 3, lch = tid & 7;      // loader: rows lrow+32i, cols lch*4..+3

    float acc[4][4][4];
#pragma unroll
    for (int mt = 0; mt < 4; mt++)
#pragma unroll
        for (int nt = 0; nt < 4; nt++)
#pragma unroll
            for (int e = 0; e < 4; e++) acc[mt][nt][e] = 0.f;

    auto ldgA = [&](float4* r, int kt) {
#pragma unroll
        for (int i = 0; i < 4; i++) {
            size_t o = (size_t)(lrow + i * 32) * K + kt + lch * 4;
            float4 v = *(const float4*)(Ab + o);
            if (As) {
                float4 s = *(const float4*)(As + o);
                v.x -= s.x; v.y -= s.y; v.z -= s.z; v.w -= s.w;
            }
            r[i] = v;
        }
    };
    auto stsA = [&](const float4* r, int s) {
        float* base = sm + s * STGF;
#pragma unroll
        for (int i = 0; i < 4; i++) {
            float4 h, l;
            fsplit(r[i].x, h.x, l.x); fsplit(r[i].y, h.y, l.y);
            fsplit(r[i].z, h.z, l.z); fsplit(r[i].w, h.w, l.w);
            int off = (lrow + i * 32) * PADF + lch * 4;
            *(float4*)(base + off)         = h;
            *(float4*)(base + PLANE + off) = l;
        }
    };
    auto cpB = [&](int s, int kt) {
        uint32_t st = sb + (uint32_t)s * (STGF * 4) + 2 * (PLANE * 4);
#pragma unroll
        for (int i = 0; i < 4; i++) {
            int row = lrow + i * 32;
            size_t o = (size_t)row * K + kt + lch * 4;
            cp16(st + row * 144 + lch * 16,                 Bh + o);
            cp16(st + (PLANE * 4) + row * 144 + lch * 16,   Bl + o);
        }
    };

    float4 ar[4];
    ldgA(ar, 0);
    cpB(0, 0); CP_COMMIT();

    // ldmatrix lane address bases (byte offsets within a plane)
    int lj = lane >> 3, li = lane & 7;
    uint32_t aoff0 = (uint32_t)(((wm * 64 + (lj & 1) * 8 + li) * PADF + ((lj >> 1) << 2)) * 4);
    uint32_t boff0 = (uint32_t)(((wn * 32 + (lj >> 1) * 8 + li) * PADF + ((lj & 1) << 2)) * 4);

    for (int t = 0; t < NT; t++) {
        stsA(ar, t & 1);
        float4 ar2[4];
        if (t + 1 < NT) {
            cpB((t + 1) & 1, (t + 1) * BKK); CP_COMMIT();
            ldgA(ar2, (t + 1) * BKK);        // latency hidden by compute(t)
            CP_WAIT1();
        } else {
            CP_WAIT0();
        }
        __syncthreads();
        uint32_t S   = sb + (uint32_t)(t & 1) * (STGF * 4);
        uint32_t pAh = S;
        uint32_t pAl = S + PLANE * 4;
        uint32_t pBh = S + 2 * (PLANE * 4);
        uint32_t pBl = S + 3 * (PLANE * 4);
#pragma unroll
        for (int kk = 0; kk < 4; kk++) {
            uint32_t koff = kk * 32;              // 8 floats
            uint32_t ah[4][4], al[4][4], bh[2][4], bl[2][4];
#pragma unroll
            for (int mt = 0; mt < 4; mt++)
                ldsm4(ah[mt], pAh + aoff0 + mt * (16 * PADF * 4) + koff);
#pragma unroll
            for (int mt = 0; mt < 4; mt++)
                ldsm4(al[mt], pAl + aoff0 + mt * (16 * PADF * 4) + koff);
#pragma unroll
            for (int np = 0; np < 2; np++)
                ldsm4(bh[np], pBh + boff0 + np * (16 * PADF * 4) + koff);
#pragma unroll
            for (int np = 0; np < 2; np++)
                ldsm4(bl[np], pBl + boff0 + np * (16 * PADF * 4) + koff);
            // term loop outermost: 16 independent accs between RAW reuses.
#pragma unroll
            for (int mt = 0; mt < 4; mt++)
#pragma unroll
                for (int nt = 0; nt < 4; nt++)
                    mma8(acc[mt][nt], ah[mt], &bl[nt >> 1][2 * (nt & 1)]);
#pragma unroll
            for (int mt = 0; mt < 4; mt++)
#pragma unroll
                for (int nt = 0; nt < 4; nt++)
                    mma8(acc[mt][nt], al[mt], &bh[nt >> 1][2 * (nt & 1)]);
#pragma unroll
            for (int mt = 0; mt < 4; mt++)
#pragma unroll
                for (int nt = 0; nt < 4; nt++)
                    mma8(acc[mt][nt], ah[mt], &bh[nt >> 1][2 * (nt & 1)]);
        }
        __syncthreads();
        if (t + 1 < NT) {
#pragma unroll
            for (int i = 0; i < 4; i++) ar[i] = ar2[i];
        }
    }

    // ---------------- epilogue ----------------
    int rowb = by * 128 + wm * 64 + (lane >> 2);
    int colb = bx * 128 + wn * 32 + 2 * (lane & 3);
#pragma unroll
    for (int mt = 0; mt < 4; mt++) {
#pragma unroll
        for (int half = 0; half < 2; half++) {
            size_t r = (size_t)(rowb + mt * 16 + half * 8);
#pragma unroll
            for (int nt = 0; nt < 4; nt++) {
                float v0 = acc[mt][nt][half * 2 + 0];
                float v1 = acc[mt][nt][half * 2 + 1];
                int gc = colb + nt * 8;
                if (mode == 0) {
                    v0 += bias[gc]; v1 += bias[gc + 1];
                    float2 v = make_float2(v0, v1);
                    *(float2*)(C  + r * 256 + gc) = v;
                    *(float2*)(C2 + r * 256 + gc) = v;
                } else if (mode == 1) {
                    *(float2*)(C + r * (size_t)ldc + gc) = make_float2(v0, v1);
                } else if (mode == 2) {
                    float t0 = tanhf(0.79788456080286535588f * (v0 + 0.044715f * v0 * v0 * v0));
                    float t1 = tanhf(0.79788456080286535588f * (v1 + 0.044715f * v1 * v1 * v1));
                    *(float2*)(C + r * 256 + gc) =
                        make_float2(0.5f * v0 * (1.f + t0), 0.5f * v1 * (1.f + t1));
                } else {
                    float t1 = v0 + bias[gc];
                    float t2 = v1 + bias[gc + 1];
                    C[r * 256 + (gc >> 1)] += t1 * (1.f / (1.f + expf(-t2)));
                }
            }
        }
    }
}

// ---------------- weight packing (transposed, K-major rows, hi/lo) -----------
__global__ void pack_kernel(const float* __restrict__ B_re, const float* __restrict__ B_im,
                            const float* __restrict__ C_re, const float* __restrict__ C_im,
                            const float* __restrict__ W1,   const float* __restrict__ W2,
                            const float* __restrict__ b1,   const float* __restrict__ b2,
                            const float* __restrict__ embW,
                            float* __restrict__ Wh, float* __restrict__ Wl)
{
    int idx = blockIdx.x * blockDim.x + threadIdx.x;
    int total = NLAYER * LSP + 65536;
    if (idx >= total) return;
    float val;
    bool is_bias = false;
    if (idx >= NLAYER * LSP) {               // embed^T: Et[n][k] = embW[k][n]
        int r = idx - NLAYER * LSP;
        int n = r >> 8, k = r & 255;
        val = embW[k * 256 + n];
    } else {
        int l = idx / LSP;
        int r = idx - l * LSP;
        if (r < 131072) {                    // Bt[j][h] = B_re/B_im[h][j]
            int j = r >> 8, h = r & 255;
            val = (j < 256) ? B_re[l * 65536 + h * 256 + j]
                            : B_im[l * 65536 + h * 256 + (j - 256)];
        } else if (r < 262144) {             // Ct[h][k] = C_re[k][h] / -C_im
            int r2 = r - 131072;
            int h = r2 >> 9, k = r2 & 511;
            val = (k < 256) ? C_re[l * 65536 + k * 256 + h]
                            : -C_im[l * 65536 + (k - 256) * 256 + h];
        } else if (r < 393216) {             // Wt[n][k], n even->W1 col n/2, odd->W2
            int r3 = r - 262144;
            int n = r3 >> 8, k = r3 & 255;
            val = (n & 1) ? W2[l * 65536 + k * 256 + (n >> 1)]
                          : W1[l * 65536 + k * 256 + (n >> 1)];
        } else {                             // interleaved bias (exact fp32)
            int n = r - 393216;
            val = (n & 1) ? b2[l * 256 + (n >> 1)] : b1[l * 256 + (n >> 1)];
            is_bias = true;
        }
    }
    if (is_bias) { Wh[idx] = val; Wl[idx] = 0.f; }
    else { float h, lo; fsplit(val, h, lo); Wh[idx] = h; Wl[idx] = lo; }
}

// ---------------- LayerNorm (one warp per row of 256), raw output ------------
__global__ void ln_kernel(const float* __restrict__ in, const float* __restrict__ scale,
                          const float* __restrict__ bias,
                          float* __restrict__ o_, int rows)
{
    int warp = (blockIdx.x * blockDim.x + threadIdx.x) >> 5;
    int lane = threadIdx.x & 31;
    if (warp >= rows) return;
    const float* x = in + (size_t)warp * 256;
    float v[8], s = 0.f;
#pragma unroll
    for (int i = 0; i < 8; i++) { v[i] = x[lane + 32 * i]; s += v[i]; }
#pragma unroll
    for (int o = 16; o; o >>= 1) s += __shfl_xor_sync(0xffffffffu, s, o);
    float mn = s * (1.f / 256.f), q = 0.f;
#pragma unroll
    for (int i = 0; i < 8; i++) { float d = v[i] - mn; q += d * d; }
#pragma unroll
    for (int o = 16; o; o >>= 1) q += __shfl_xor_sync(0xffffffffu, q, o);
    float inv = rsqrtf(q * (1.f / 256.f) + 1e-5f);
#pragma unroll
    for (int i = 0; i < 8; i++) {
        int h = lane + 32 * i;
        o_[(size_t)warp * 256 + h] = (v[i] - mn) * inv * scale[h] + bias[h];
    }
}

// ---------------- complex affine scan along N --------------------------------
// grid (16 pg, 16 b), block 256 = 16 p-lanes x 16 chunks of 128 steps.
// Emits ONLY x_right (raw fp32); x_left is derived in the C-GEMM as X - Bu.
// Precise expf for magnitude; Taylor sin/cos for the bounded phase.
__global__ __launch_bounds__(256) void scan_kernel(
    const float* __restrict__ Bu, const float* __restrict__ dt,
    const float* __restrict__ Lre, const float* __restrict__ Lim,
    const float* __restrict__ logdelta,
    const float* __restrict__ ire, const float* __restrict__ iim,
    float* __restrict__ X)
{
    __shared__ float dts[SEQ];
    __shared__ float agg[16][16][4];
    __shared__ float carry[16][16][2];
    int b = blockIdx.y, pg = blockIdx.x;
    int tid = threadIdx.x;
    int pl = tid & 15, c = tid >> 4;
    int p = pg * 16 + pl;

    for (int i = tid; i < SEQ; i += 256) dts[i] = dt[b * SEQ + i];
    float nE = -expf(Lre[p]);
    float lim = Lim[p];
    float del = expf(logdelta[p]);
    __syncthreads();

    int n0 = c * 128;
    size_t rowbase = ((size_t)b * SEQ + n0) * 512 + p;
    const float* bup = Bu + rowbase;

    // phase 1: chunk aggregates with zero initial state
    float Ar = 1.f, Ai = 0.f, Xr = 0.f, Xi = 0.f;
    for (int j = 0; j < 128; j++) {
        float dte = dts[n0 + j] * del;
        float mag = expf(nE * dte);
        float th = lim * dte;
        float ar = mag * cos_poly(th), ai = mag * sin_poly(th);
        float br = bup[(size_t)j * 512], bi = bup[(size_t)j * 512 + 256];
        float nAr = Ar * ar - Ai * ai, nAi = Ar * ai + Ai * ar;
        float nXr = Xr * ar - Xi * ai + br, nXi = Xr * ai + Xi * ar + bi;
        Ar = nAr; Ai = nAi; Xr = nXr; Xi = nXi;
    }
    agg[c][pl][0] = Ar; agg[c][pl][1] = Ai; agg[c][pl][2] = Xr; agg[c][pl][3] = Xi;
    __syncthreads();

    // serial carry across 16 chunks (threads 0..15), x0 injection via init
    if (c == 0) {
        float cr = ire[p], ci = iim[p];
        carry[0][pl][0] = cr; carry[0][pl][1] = ci;
        for (int cc = 1; cc < 16; cc++) {
            float Aor = agg[cc-1][pl][0], Aoi = agg[cc-1][pl][1];
            float Xor_ = agg[cc-1][pl][2], Xoi = agg[cc-1][pl][3];
            float nr = Aor * cr - Aoi * ci + Xor_;
            float ni = Aor * ci + Aoi * cr + Xoi;
            cr = nr; ci = ni;
            carry[cc][pl][0] = cr; carry[cc][pl][1] = ci;
        }
    }
    __syncthreads();

    // phase 2: replay with true carry; emit x_right only
    float xr = carry[c][pl][0], xi = carry[c][pl][1];
    for (int j = 0; j < 128; j++) {
        float dte = dts[n0 + j] * del;
        float mag = expf(nE * dte);
        float th = lim * dte;
        float ar = mag * cos_poly(th), ai = mag * sin_poly(th);
        float br = bup[(size_t)j * 512], bi = bup[(size_t)j * 512 + 256];
        float lr = ar * xr - ai * xi, li2 = ar * xi + ai * xr;   // left limit
        float rr = lr + br,           ri  = li2 + bi;            // right limit
        size_t o = rowbase + (size_t)j * 512;
        X[o]       = rr;
        X[o + 256] = ri;
        xr = rr; xi = ri;
    }
}

__global__ void out_kernel(const float* __restrict__ Uleft, float* __restrict__ out, int n)
{
    int i = blockIdx.x * blockDim.x + threadIdx.x;
    if (i < n) {
        int row = i >> 8;
        int nn = row & (SEQ - 1);
        out[i] = (nn == 0) ? 0.f : Uleft[i];
    }
}

// ---------------- driver -----------------------------------------------------
extern "C" void kernel_launch(void* const* d_in, const int* in_sizes, int n_in,
                              void* d_out, int out_size)
{
    (void)in_sizes; (void)n_in; (void)out_size;
    const float* x_payload = (const float*)d_in[0];
    const float* dt        = (const float*)d_in[1];
    const float* embed_W   = (const float*)d_in[2];
    const float* embed_b   = (const float*)d_in[3];
    const float* ln_scale  = (const float*)d_in[4];
    const float* ln_bias   = (const float*)d_in[5];
    const float* Lambda_re = (const float*)d_in[6];
    const float* Lambda_im = (const float*)d_in[7];
    const float* log_delta = (const float*)d_in[8];
    const float* B_re      = (const float*)d_in[9];
    const float* B_im      = (const float*)d_in[10];
    const float* C_re      = (const float*)d_in[11];
    const float* C_im      = (const float*)d_in[12];
    const float* W1        = (const float*)d_in[13];
    const float* b1        = (const float*)d_in[14];
    const float* W2        = (const float*)d_in[15];
    const float* b2        = (const float*)d_in[16];
    const float* init_re   = (const float*)d_in[17];
    const float* init_im   = (const float*)d_in[18];
    float* out = (float*)d_out;

    float *V, *Bu, *X, *Y, *U, *Wh, *Wl;
    cudaGetSymbolAddress((void**)&V,  g_V);
    cudaGetSymbolAddress((void**)&Bu, g_Bu);
    cudaGetSymbolAddress((void**)&X,  g_X);
    cudaGetSymbolAddress((void**)&Y,  g_Y);
    cudaGetSymbolAddress((void**)&U,  g_U);
    cudaGetSymbolAddress((void**)&Wh, g_Wh);
    cudaGetSymbolAddress((void**)&Wl, g_Wl);

    cudaFuncSetAttribute(gemm_mma, cudaFuncAttributeMaxDynamicSharedMemorySize, GSMEM);

    {
        int total = NLAYER * LSP + 65536;
        pack_kernel<<<(total + 255) / 256, 256>>>(B_re, B_im, C_re, C_im, W1, W2,
                                                  b1, b2, embed_W, Wh, Wl);
    }

    const int n1 = BNTOT * 256;
    const int BIG = 1 << 30;
    float* EmbH = Wh + (size_t)NLAYER * LSP;
    float* EmbL = Wl + (size_t)NLAYER * LSP;
    float* U1   = U + (size_t)BNTOT * 256;

    // alpha = x @ embed_W + b -> right_u and left_u   (mode 0)
    gemm_mma<<<dim3(2, 256), 256, GSMEM>>>(x_payload, nullptr, EmbH, EmbL,
                                           embed_b, U, U1, 256, 256, 0, BIG);

    for (int l = 0; l < NLAYER; l++) {
        size_t wo = (size_t)l * LSP;
        ln_kernel<<<4096, 256>>>(U, ln_scale + l * 256, ln_bias + l * 256, V, BNTOT);
        // Bu = v @ [B_re|B_im]   (mode 1, out stride 512)
        gemm_mma<<<dim3(4, 256), 256, GSMEM>>>(V, nullptr, Wh + wo, Wl + wo,
                                               nullptr, Bu, nullptr, 512, 256, 1, BIG);
        scan_kernel<<<dim3(16, 16), 256>>>(Bu, dt,
                                           Lambda_re + l * 256, Lambda_im + l * 256,
                                           log_delta + l * 256,
                                           init_re + l * 256, init_im + l * 256, X);
        // g = gelu([x_right; x_left] @ [C_re;-C_im]); left rows derived as X - Bu
        // N = 256 -> bx in {0,1}  (R12 bug: grid.x was 1, half of Y never computed)
        gemm_mma<<<dim3(2, 512), 256, GSMEM>>>(X, Bu, Wh + wo + 131072, Wl + wo + 131072,
                                               nullptr, Y, nullptr, 256, 512, 2, 256);
        // U += (g@W1+b1)*sigmoid(g@W2+b2)  (mode 3, interleaved columns)
        gemm_mma<<<dim3(4, 512), 256, GSMEM>>>(Y, nullptr, Wh + wo + 262144, Wl + wo + 262144,
                                               Wh + wo + 393216, U, nullptr, 256, 256, 3, BIG);
    }

    out_kernel<<<(n1 + 255) / 256, 256>>>(U1, out, n1);
}

// round 16
// speedup vs baseline: 1.0835x; 1.0835x over previous
#include <cuda_runtime.h>
#include <cuda_bf16.h>
#include <cstdint>
#include <math.h>

// Problem constants
#define BATCH 16
#define SEQ   2048
#define NLAYER 4
#define BNTOT (BATCH*SEQ)          // 32768
#define LSP   393728               // packed per-layer weight stride (floats)

// ---------------- scratch (device globals) ----------------------------------
__device__ float g_Vh[(size_t)BNTOT*256];        // LN output hi
__device__ float g_Vl[(size_t)BNTOT*256];        // LN output lo
__device__ float g_Bu[(size_t)BNTOT*512];        // [Bu_re | Bu_im]
__device__ float g_Xh[(size_t)2*BNTOT*512];      // scan out hi (right rows 0.., left rows BN..)
__device__ float g_Xl[(size_t)2*BNTOT*512];      // scan out lo
__device__ float g_Yh[(size_t)2*BNTOT*256];      // gelu(y) hi
__device__ float g_Yl[(size_t)2*BNTOT*256];      // gelu(y) lo
__device__ float g_U [(size_t)2*BNTOT*256];      // right_u rows 0.., left_u rows BN..
__device__ float g_Wh[(size_t)NLAYER*LSP + 65536]; // packed weights hi (+embed)
__device__ float g_Wl[(size_t)NLAYER*LSP + 65536]; // packed weights lo
__device__ float g_Ph[(size_t)BNTOT*256];        // x_payload hi
__device__ float g_Pl[(size_t)BNTOT*256];        // x_payload lo

// ---------------- helpers ----------------------------------------------------
static __device__ __forceinline__ uint32_t smem_u32(const void* p) {
    uint32_t a;
    asm("{ .reg .u64 t; cvta.to.shared.u64 t, %1; cvt.u32.u64 %0, t; }" : "=r"(a) : "l"(p));
    return a;
}
static __device__ __forceinline__ void cp16(uint32_t dst, const void* src) {
    asm volatile("cp.async.cg.shared.global [%0], [%1], 16;" :: "r"(dst), "l"(src));
}
#define CP_COMMIT() asm volatile("cp.async.commit_group;" ::: "memory")
#define CP_WAIT1()  asm volatile("cp.async.wait_group 1;" ::: "memory")
#define CP_WAIT0()  asm volatile("cp.async.wait_group 0;" ::: "memory")

static __device__ __forceinline__ uint32_t to_tf32(float x) {
    uint32_t r;
    asm("cvt.rna.tf32.f32 %0, %1;" : "=r"(r) : "f"(x));
    return r;
}
// split x into tf32-rounded hi + lo, stored as fp32 words
static __device__ __forceinline__ void fsplit(float x, float& hi, float& lo) {
    hi = __uint_as_float(to_tf32(x));
    lo = __uint_as_float(to_tf32(x - hi));
}
static __device__ __forceinline__ void mma8(float* c, const uint32_t* a, const uint32_t* b) {
    asm volatile("mma.sync.aligned.m16n8k8.row.col.f32.tf32.tf32.f32 "
                 "{%0,%1,%2,%3}, {%4,%5,%6,%7}, {%8,%9}, {%0,%1,%2,%3};"
                 : "+f"(c[0]), "+f"(c[1]), "+f"(c[2]), "+f"(c[3])
                 : "r"(a[0]), "r"(a[1]), "r"(a[2]), "r"(a[3]), "r"(b[0]), "r"(b[1]));
}
static __device__ __forceinline__ void ldsm4(uint32_t* r, uint32_t addr) {
    asm volatile("ldmatrix.sync.aligned.m8n8.x4.shared.b16 {%0,%1,%2,%3}, [%4];"
                 : "=r"(r[0]), "=r"(r[1]), "=r"(r[2]), "=r"(r[3]) : "r"(addr));
}

// Taylor sin/cos for |t| <= ~1.3 (scan phase bounded by |Lam_im|*dt*delta).
// Truncation <= 3e-9 (library accuracy). Validated in R13: rel_err identical
// to sincosf baseline (8.91e-5 vs 8.93e-5).
static __device__ __forceinline__ float sin_poly(float t) {
    float t2 = t * t;
    float p = -2.5052108e-8f;
    p = fmaf(p, t2,  2.7557319e-6f);
    p = fmaf(p, t2, -1.9841270e-4f);
    p = fmaf(p, t2,  8.3333333e-3f);
    p = fmaf(p, t2, -0.16666667f);
    p = fmaf(p, t2,  1.0f);
    return t * p;
}
static __device__ __forceinline__ float cos_poly(float t) {
    float t2 = t * t;
    float p = 2.0876757e-9f;
    p = fmaf(p, t2, -2.7557319e-7f);
    p = fmaf(p, t2,  2.4801587e-5f);
    p = fmaf(p, t2, -1.3888889e-3f);
    p = fmaf(p, t2,  4.1666667e-2f);
    p = fmaf(p, t2, -0.5f);
    p = fmaf(p, t2,  1.0f);
    return p;
}

// ---------------- 3xTF32 mma.sync GEMM, pre-split operands, ldmatrix ---------
// C(128x128 per CTA) = A(M x K) @ Bt(N x K)^T
// 8 warps (2m x 4n), warp tile 64x32, BK=32, 2-stage cp.async pipeline.
// SMEM per stage: Ah | Al | Bh | Bl planes (128 rows x 36 floats each).
// Epilogue modes:
//  0: +bias, dual store to C and C2 (embed -> right_u/left_u)
//  1: plain store, row stride ldc (Bu)
//  2: gelu then split-store hi->C, lo->C2, stride 256
//  3: interleaved GLU pairs: C[r][gc/2] += (t1+b1)*sigmoid(t2+b2)
#define BKK   32
#define PADF  36                         // floats per smem row (144B, 16B-aligned)
#define PLANE (128*PADF)                 // one operand plane (floats)
#define STGF  (4*PLANE)                  // stage floats (Ah,Al,Bh,Bl)
#define GSMEM (2*STGF*4)                 // 147456 bytes

static __device__ __forceinline__ void load_stage(uint32_t sb, int s,
                                                  const float* Ah, const float* Al,
                                                  const float* Bh, const float* Bl,
                                                  int K, int kt, int tid) {
    uint32_t st = sb + (uint32_t)s * (STGF * 4);
    const float* srcs[4] = { Ah, Al, Bh, Bl };
#pragma unroll
    for (int pl = 0; pl < 4; pl++) {
        const float* src = srcs[pl];
        uint32_t base = st + pl * (PLANE * 4);
#pragma unroll
        for (int i = 0; i < 4; i++) {        // 128 rows x 8 float4 = 1024 f4 / 256 thr
            int f = tid + i * 256;
            int row = f >> 3, ch = f & 7;
            cp16(base + row * 144 + ch * 16, src + (size_t)row * K + kt + ch * 4);
        }
    }
}

__global__ __launch_bounds__(256, 1) void gemm_mma(
    const float* __restrict__ Ahi, const float* __restrict__ Alo,
    const float* __restrict__ Bhi, const float* __restrict__ Blo,
    const float* __restrict__ bias, float* __restrict__ C, float* __restrict__ C2,
    int ldc, int K, int mode)
{
    extern __shared__ float sm[];
    uint32_t sb = smem_u32(sm);
    int tid = threadIdx.x;
    int warp = tid >> 5, lane = tid & 31;
    int wm = warp & 1, wn = warp >> 1;
    int bx = blockIdx.x, by = blockIdx.y;

    const size_t aoff = (size_t)by * 128 * K;
    const size_t boff = (size_t)bx * 128 * K;
    const float* Ah = Ahi + aoff; const float* Al = Alo + aoff;
    const float* Bh = Bhi + boff; const float* Bl = Blo + boff;
    int NT = K / BKK;

    float acc[4][4][4];
#pragma unroll
    for (int mt = 0; mt < 4; mt++)
#pragma unroll
        for (int nt = 0; nt < 4; nt++)
#pragma unroll
            for (int e = 0; e < 4; e++) acc[mt][nt][e] = 0.f;

    load_stage(sb, 0, Ah, Al, Bh, Bl, K, 0, tid); CP_COMMIT();

    // ldmatrix lane address bases (byte offsets within a plane)
    int lj = lane >> 3, li = lane & 7;
    uint32_t aoff0 = (uint32_t)(((wm * 64 + (lj & 1) * 8 + li) * PADF + ((lj >> 1) << 2)) * 4);
    uint32_t boff0 = (uint32_t)(((wn * 32 + (lj >> 1) * 8 + li) * PADF + ((lj & 1) << 2)) * 4);

    for (int t = 0; t < NT; t++) {
        if (t + 1 < NT) {
            load_stage(sb, (t + 1) & 1, Ah, Al, Bh, Bl, K, (t + 1) * BKK, tid);
            CP_COMMIT(); CP_WAIT1();
        } else {
            CP_WAIT0();
        }
        __syncthreads();
        uint32_t S   = sb + (uint32_t)(t & 1) * (STGF * 4);
        uint32_t pAh = S;
        uint32_t pAl = S + PLANE * 4;
        uint32_t pBh = S + 2 * (PLANE * 4);
        uint32_t pBl = S + 3 * (PLANE * 4);
#pragma unroll
        for (int kk = 0; kk < 4; kk++) {
            uint32_t koff = kk * 32;              // 8 floats
            uint32_t ah[4][4], al[4][4], bh[2][4], bl[2][4];
#pragma unroll
            for (int mt = 0; mt < 4; mt++)
                ldsm4(ah[mt], pAh + aoff0 + mt * (16 * PADF * 4) + koff);
#pragma unroll
            for (int mt = 0; mt < 4; mt++)
                ldsm4(al[mt], pAl + aoff0 + mt * (16 * PADF * 4) + koff);
#pragma unroll
            for (int np = 0; np < 2; np++)
                ldsm4(bh[np], pBh + boff0 + np * (16 * PADF * 4) + koff);
#pragma unroll
            for (int np = 0; np < 2; np++)
                ldsm4(bl[np], pBl + boff0 + np * (16 * PADF * 4) + koff);
            // term loop outermost: 16 independent accs between RAW reuses.
            // per-acc order: ah*bl, al*bh, ah*bh (dominant last).
#pragma unroll
            for (int mt = 0; mt < 4; mt++)
#pragma unroll
                for (int nt = 0; nt < 4; nt++)
                    mma8(acc[mt][nt], ah[mt], &bl[nt >> 1][2 * (nt & 1)]);
#pragma unroll
            for (int mt = 0; mt < 4; mt++)
#pragma unroll
                for (int nt = 0; nt < 4; nt++)
                    mma8(acc[mt][nt], al[mt], &bh[nt >> 1][2 * (nt & 1)]);
#pragma unroll
            for (int mt = 0; mt < 4; mt++)
#pragma unroll
                for (int nt = 0; nt < 4; nt++)
                    mma8(acc[mt][nt], ah[mt], &bh[nt >> 1][2 * (nt & 1)]);
        }
        __syncthreads();
    }

    // ---------------- epilogue ----------------
    int rowb = by * 128 + wm * 64 + (lane >> 2);
    int colb = bx * 128 + wn * 32 + 2 * (lane & 3);
#pragma unroll
    for (int mt = 0; mt < 4; mt++) {
#pragma unroll
        for (int half = 0; half < 2; half++) {
            size_t r = (size_t)(rowb + mt * 16 + half * 8);
#pragma unroll
            for (int nt = 0; nt < 4; nt++) {
                float v0 = acc[mt][nt][half * 2 + 0];
                float v1 = acc[mt][nt][half * 2 + 1];
                int gc = colb + nt * 8;
                if (mode == 0) {
                    v0 += bias[gc]; v1 += bias[gc + 1];
                    float2 v = make_float2(v0, v1);
                    *(float2*)(C  + r * 256 + gc) = v;
                    *(float2*)(C2 + r * 256 + gc) = v;
                } else if (mode == 1) {
                    *(float2*)(C + r * (size_t)ldc + gc) = make_float2(v0, v1);
                } else if (mode == 2) {
                    float t0 = tanhf(0.79788456080286535588f * (v0 + 0.044715f * v0 * v0 * v0));
                    float t1 = tanhf(0.79788456080286535588f * (v1 + 0.044715f * v1 * v1 * v1));
                    float g0 = 0.5f * v0 * (1.f + t0);
                    float g1 = 0.5f * v1 * (1.f + t1);
                    float h0, l0, h1, l1;
                    fsplit(g0, h0, l0); fsplit(g1, h1, l1);
                    *(float2*)(C  + r * 256 + gc) = make_float2(h0, h1);
                    *(float2*)(C2 + r * 256 + gc) = make_float2(l0, l1);
                } else {
                    float t1 = v0 + bias[gc];
                    float t2 = v1 + bias[gc + 1];
                    C[r * 256 + (gc >> 1)] += t1 * (1.f / (1.f + expf(-t2)));
                }
            }
        }
    }
}

// ---------------- weight packing (transposed, K-major rows, hi/lo) -----------
__global__ void pack_kernel(const float* __restrict__ B_re, const float* __restrict__ B_im,
                            const float* __restrict__ C_re, const float* __restrict__ C_im,
                            const float* __restrict__ W1,   const float* __restrict__ W2,
                            const float* __restrict__ b1,   const float* __restrict__ b2,
                            const float* __restrict__ embW,
                            float* __restrict__ Wh, float* __restrict__ Wl)
{
    int idx = blockIdx.x * blockDim.x + threadIdx.x;
    int total = NLAYER * LSP + 65536;
    if (idx >= total) return;
    float val;
    bool is_bias = false;
    if (idx >= NLAYER * LSP) {               // embed^T: Et[n][k] = embW[k][n]
        int r = idx - NLAYER * LSP;
        int n = r >> 8, k = r & 255;
        val = embW[k * 256 + n];
    } else {
        int l = idx / LSP;
        int r = idx - l * LSP;
        if (r < 131072) {                    // Bt[j][h] = B_re/B_im[h][j]
            int j = r >> 8, h = r & 255;
            val = (j < 256) ? B_re[l * 65536 + h * 256 + j]
                            : B_im[l * 65536 + h * 256 + (j - 256)];
        } else if (r < 262144) {             // Ct[h][k] = C_re[k][h] / -C_im
            int r2 = r - 131072;
            int h = r2 >> 9, k = r2 & 511;
            val = (k < 256) ? C_re[l * 65536 + k * 256 + h]
                            : -C_im[l * 65536 + (k - 256) * 256 + h];
        } else if (r < 393216) {             // Wt[n][k], n even->W1 col n/2, odd->W2
            int r3 = r - 262144;
            int n = r3 >> 8, k = r3 & 255;
            val = (n & 1) ? W2[l * 65536 + k * 256 + (n >> 1)]
                          : W1[l * 65536 + k * 256 + (n >> 1)];
        } else {                             // interleaved bias (exact fp32)
            int n = r - 393216;
            val = (n & 1) ? b2[l * 256 + (n >> 1)] : b1[l * 256 + (n >> 1)];
            is_bias = true;
        }
    }
    if (is_bias) { Wh[idx] = val; Wl[idx] = 0.f; }
    else { float h, lo; fsplit(val, h, lo); Wh[idx] = h; Wl[idx] = lo; }
}

// ---------------- x_payload split --------------------------------------------
__global__ void split_kernel(const float* __restrict__ x,
                             float* __restrict__ hi, float* __restrict__ lo, int n)
{
    int i = blockIdx.x * blockDim.x + threadIdx.x;
    if (i < n) { float h, l; fsplit(x[i], h, l); hi[i] = h; lo[i] = l; }
}

// ---------------- LayerNorm (one warp per row of 256), split output ----------
__global__ void ln_kernel(const float* __restrict__ in, const float* __restrict__ scale,
                          const float* __restrict__ bias,
                          float* __restrict__ oh, float* __restrict__ ol, int rows)
{
    int warp = (blockIdx.x * blockDim.x + threadIdx.x) >> 5;
    int lane = threadIdx.x & 31;
    if (warp >= rows) return;
    const float* x = in + (size_t)warp * 256;
    float v[8], s = 0.f;
#pragma unroll
    for (int i = 0; i < 8; i++) { v[i] = x[lane + 32 * i]; s += v[i]; }
#pragma unroll
    for (int o = 16; o; o >>= 1) s += __shfl_xor_sync(0xffffffffu, s, o);
    float mn = s * (1.f / 256.f), q = 0.f;
#pragma unroll
    for (int i = 0; i < 8; i++) { float d = v[i] - mn; q += d * d; }
#pragma unroll
    for (int o = 16; o; o >>= 1) q += __shfl_xor_sync(0xffffffffu, q, o);
    float inv = rsqrtf(q * (1.f / 256.f) + 1e-5f);
#pragma unroll
    for (int i = 0; i < 8; i++) {
        int h = lane + 32 * i;
        float y = (v[i] - mn) * inv * scale[h] + bias[h];
        float yh, yl; fsplit(y, yh, yl);
        oh[(size_t)warp * 256 + h] = yh;
        ol[(size_t)warp * 256 + h] = yl;
    }
}

// ---------------- complex affine scan along N, split output ------------------
// grid (16 pg, 16 b), block 256 = 16 p-lanes x 16 chunks of 128 steps.
// Precise expf for magnitude; Taylor polys (validated R13) for bounded phase.
__global__ __launch_bounds__(256) void scan_kernel(
    const float* __restrict__ Bu, const float* __restrict__ dt,
    const float* __restrict__ Lre, const float* __restrict__ Lim,
    const float* __restrict__ logdelta,
    const float* __restrict__ ire, const float* __restrict__ iim,
    float* __restrict__ Xh, float* __restrict__ Xl)
{
    __shared__ float dts[SEQ];
    __shared__ float agg[16][16][4];
    __shared__ float carry[16][16][2];
    int b = blockIdx.y, pg = blockIdx.x;
    int tid = threadIdx.x;
    int pl = tid & 15, c = tid >> 4;
    int p = pg * 16 + pl;

    for (int i = tid; i < SEQ; i += 256) dts[i] = dt[b * SEQ + i];
    float nE = -expf(Lre[p]);
    float lim = Lim[p];
    float del = expf(logdelta[p]);
    __syncthreads();

    int n0 = c * 128;
    size_t rowbase = ((size_t)b * SEQ + n0) * 512 + p;
    const float* bup = Bu + rowbase;

    // phase 1: chunk aggregates with zero initial state
    float Ar = 1.f, Ai = 0.f, Xr = 0.f, Xi = 0.f;
    for (int j = 0; j < 128; j++) {
        float dte = dts[n0 + j] * del;
        float mag = expf(nE * dte);
        float th = lim * dte;
        float ar = mag * cos_poly(th), ai = mag * sin_poly(th);
        float br = bup[(size_t)j * 512], bi = bup[(size_t)j * 512 + 256];
        float nAr = Ar * ar - Ai * ai, nAi = Ar * ai + Ai * ar;
        float nXr = Xr * ar - Xi * ai + br, nXi = Xr * ai + Xi * ar + bi;
        Ar = nAr; Ai = nAi; Xr = nXr; Xi = nXi;
    }
    agg[c][pl][0] = Ar; agg[c][pl][1] = Ai; agg[c][pl][2] = Xr; agg[c][pl][3] = Xi;
    __syncthreads();

    // serial carry across 16 chunks (threads 0..15), x0 injection via init
    if (c == 0) {
        float cr = ire[p], ci = iim[p];
        carry[0][pl][0] = cr; carry[0][pl][1] = ci;
        for (int cc = 1; cc < 16; cc++) {
            float Aor = agg[cc-1][pl][0], Aoi = agg[cc-1][pl][1];
            float Xor_ = agg[cc-1][pl][2], Xoi = agg[cc-1][pl][3];
            float nr = Aor * cr - Aoi * ci + Xor_;
            float ni = Aor * ci + Aoi * cr + Xoi;
            cr = nr; ci = ni;
            carry[cc][pl][0] = cr; carry[cc][pl][1] = ci;
        }
    }
    __syncthreads();

    // phase 2: replay with true carry; emit x_left = a*x_prev, x_right = x_left + Bu
    float xr = carry[c][pl][0], xi = carry[c][pl][1];
    const size_t LHALF = (size_t)BNTOT * 512;
    for (int j = 0; j < 128; j++) {
        float dte = dts[n0 + j] * del;
        float mag = expf(nE * dte);
        float th = lim * dte;
        float ar = mag * cos_poly(th), ai = mag * sin_poly(th);
        float br = bup[(size_t)j * 512], bi = bup[(size_t)j * 512 + 256];
        float lr = ar * xr - ai * xi, li2 = ar * xi + ai * xr;   // left limit
        float rr = lr + br,           ri  = li2 + bi;            // right limit
        float h, l;
        size_t o = rowbase + (size_t)j * 512;
        fsplit(lr,  h, l); Xh[LHALF + o]       = h; Xl[LHALF + o]       = l;
        fsplit(li2, h, l); Xh[LHALF + o + 256] = h; Xl[LHALF + o + 256] = l;
        fsplit(rr,  h, l); Xh[o]               = h; Xl[o]               = l;
        fsplit(ri,  h, l); Xh[o + 256]         = h; Xl[o + 256]         = l;
        xr = rr; xi = ri;
    }
}

__global__ void out_kernel(const float* __restrict__ Uleft, float* __restrict__ out, int n)
{
    int i = blockIdx.x * blockDim.x + threadIdx.x;
    if (i < n) {
        int row = i >> 8;
        int nn = row & (SEQ - 1);
        out[i] = (nn == 0) ? 0.f : Uleft[i];
    }
}

// ---------------- driver -----------------------------------------------------
extern "C" void kernel_launch(void* const* d_in, const int* in_sizes, int n_in,
                              void* d_out, int out_size)
{
    (void)in_sizes; (void)n_in; (void)out_size;
    const float* x_payload = (const float*)d_in[0];
    const float* dt        = (const float*)d_in[1];
    const float* embed_W   = (const float*)d_in[2];
    const float* embed_b   = (const float*)d_in[3];
    const float* ln_scale  = (const float*)d_in[4];
    const float* ln_bias   = (const float*)d_in[5];
    const float* Lambda_re = (const float*)d_in[6];
    const float* Lambda_im = (const float*)d_in[7];
    const float* log_delta = (const float*)d_in[8];
    const float* B_re      = (const float*)d_in[9];
    const float* B_im      = (const float*)d_in[10];
    const float* C_re      = (const float*)d_in[11];
    const float* C_im      = (const float*)d_in[12];
    const float* W1        = (const float*)d_in[13];
    const float* b1        = (const float*)d_in[14];
    const float* W2        = (const float*)d_in[15];
    const float* b2        = (const float*)d_in[16];
    const float* init_re   = (const float*)d_in[17];
    const float* init_im   = (const float*)d_in[18];
    float* out = (float*)d_out;

    float *Vh, *Vl, *Bu, *Xh, *Xl, *Yh, *Yl, *U, *Wh, *Wl, *Ph, *Pl;
    cudaGetSymbolAddress((void**)&Vh, g_Vh);
    cudaGetSymbolAddress((void**)&Vl, g_Vl);
    cudaGetSymbolAddress((void**)&Bu, g_Bu);
    cudaGetSymbolAddress((void**)&Xh, g_Xh);
    cudaGetSymbolAddress((void**)&Xl, g_Xl);
    cudaGetSymbolAddress((void**)&Yh, g_Yh);
    cudaGetSymbolAddress((void**)&Yl, g_Yl);
    cudaGetSymbolAddress((void**)&U,  g_U);
    cudaGetSymbolAddress((void**)&Wh, g_Wh);
    cudaGetSymbolAddress((void**)&Wl, g_Wl);
    cudaGetSymbolAddress((void**)&Ph, g_Ph);
    cudaGetSymbolAddress((void**)&Pl, g_Pl);

    cudaFuncSetAttribute(gemm_mma, cudaFuncAttributeMaxDynamicSharedMemorySize, GSMEM);

    {
        int total = NLAYER * LSP + 65536;
        pack_kernel<<<(total + 255) / 256, 256>>>(B_re, B_im, C_re, C_im, W1, W2,
                                                  b1, b2, embed_W, Wh, Wl);
    }
    const int n1 = BNTOT * 256;
    split_kernel<<<(n1 + 255) / 256, 256>>>(x_payload, Ph, Pl, n1);

    float* EmbH = Wh + (size_t)NLAYER * LSP;
    float* EmbL = Wl + (size_t)NLAYER * LSP;
    float* U1   = U + (size_t)BNTOT * 256;

    // alpha = x @ embed_W + b -> right_u and left_u   (mode 0)
    gemm_mma<<<dim3(2, 256), 256, GSMEM>>>(Ph, Pl, EmbH, EmbL, embed_b, U, U1, 256, 256, 0);

    for (int l = 0; l < NLAYER; l++) {
        size_t wo = (size_t)l * LSP;
        ln_kernel<<<4096, 256>>>(U, ln_scale + l * 256, ln_bias + l * 256, Vh, Vl, BNTOT);
        // Bu = v @ [B_re|B_im]   (mode 1, out stride 512)
        gemm_mma<<<dim3(4, 256), 256, GSMEM>>>(Vh, Vl, Wh + wo, Wl + wo,
                                               nullptr, Bu, nullptr, 512, 256, 1);
        scan_kernel<<<dim3(16, 16), 256>>>(Bu, dt,
                                           Lambda_re + l * 256, Lambda_im + l * 256,
                                           log_delta + l * 256,
                                           init_re + l * 256, init_im + l * 256, Xh, Xl);
        // g = gelu(X @ [C_re;-C_im])   (mode 2, both streams stacked on M)
        gemm_mma<<<dim3(2, 512), 256, GSMEM>>>(Xh, Xl, Wh + wo + 131072, Wl + wo + 131072,
                                               nullptr, Yh, Yl, 256, 512, 2);
        // U += (g@W1+b1)*sigmoid(g@W2+b2)  (mode 3, interleaved columns)
        gemm_mma<<<dim3(4, 512), 256, GSMEM>>>(Yh, Yl, Wh + wo + 262144, Wl + wo + 262144,
                                               Wh + wo + 393216, U, nullptr, 256, 256, 3);
    }

    out_kernel<<<(n1 + 255) / 256, 256>>>(U1, out, n1);
}

// round 17
// speedup vs baseline: 1.8595x; 1.7162x over previous
#include <cuda_runtime.h>
#include <cuda_bf16.h>
#include <cstdint>
#include <math.h>

// Problem constants
#define BATCH 16
#define SEQ   2048
#define NLAYER 4
#define BNTOT (BATCH*SEQ)          // 32768
#define LSP   393728               // packed per-layer weight stride (floats)

// ---------------- scratch (device globals) ----------------------------------
__device__ float g_Vh[(size_t)BNTOT*256];        // LN output hi
__device__ float g_Vl[(size_t)BNTOT*256];        // LN output lo
__device__ float g_Bu[(size_t)BNTOT*512];        // [Bu_re | Bu_im]
__device__ float g_Xh[(size_t)2*BNTOT*512];      // scan out hi (right rows 0.., left rows BN..)
__device__ float g_Xl[(size_t)2*BNTOT*512];      // scan out lo
__device__ float g_Yh[(size_t)2*BNTOT*256];      // gelu(y) hi
__device__ float g_Yl[(size_t)2*BNTOT*256];      // gelu(y) lo
__device__ float g_U [(size_t)2*BNTOT*256];      // right_u rows 0.., left_u rows BN..
__device__ float g_Wh[(size_t)NLAYER*LSP + 65536]; // packed weights hi (+embed)
__device__ float g_Wl[(size_t)NLAYER*LSP + 65536]; // packed weights lo
__device__ float g_Ph[(size_t)BNTOT*256];        // x_payload hi
__device__ float g_Pl[(size_t)BNTOT*256];        // x_payload lo

// ---------------- helpers ----------------------------------------------------
static __device__ __forceinline__ uint32_t smem_u32(const void* p) {
    uint32_t a;
    asm("{ .reg .u64 t; cvta.to.shared.u64 t, %1; cvt.u32.u64 %0, t; }" : "=r"(a) : "l"(p));
    return a;
}
static __device__ __forceinline__ void cp16(uint32_t dst, const void* src) {
    asm volatile("cp.async.cg.shared.global [%0], [%1], 16;" :: "r"(dst), "l"(src));
}
#define CP_COMMIT() asm volatile("cp.async.commit_group;" ::: "memory")
#define CP_WAIT1()  asm volatile("cp.async.wait_group 1;" ::: "memory")
#define CP_WAIT0()  asm volatile("cp.async.wait_group 0;" ::: "memory")

static __device__ __forceinline__ uint32_t to_tf32(float x) {
    uint32_t r;
    asm("cvt.rna.tf32.f32 %0, %1;" : "=r"(r) : "f"(x));
    return r;
}
// split x into tf32-rounded hi + lo, stored as fp32 words
static __device__ __forceinline__ void fsplit(float x, float& hi, float& lo) {
    hi = __uint_as_float(to_tf32(x));
    lo = __uint_as_float(to_tf32(x - hi));
}
static __device__ __forceinline__ void mma8(float* c, const uint32_t* a, const uint32_t* b) {
    asm volatile("mma.sync.aligned.m16n8k8.row.col.f32.tf32.tf32.f32 "
                 "{%0,%1,%2,%3}, {%4,%5,%6,%7}, {%8,%9}, {%0,%1,%2,%3};"
                 : "+f"(c[0]), "+f"(c[1]), "+f"(c[2]), "+f"(c[3])
                 : "r"(a[0]), "r"(a[1]), "r"(a[2]), "r"(a[3]), "r"(b[0]), "r"(b[1]));
}
static __device__ __forceinline__ void ldsm4(uint32_t* r, uint32_t addr) {
    asm volatile("ldmatrix.sync.aligned.m8n8.x4.shared.b16 {%0,%1,%2,%3}, [%4];"
                 : "=r"(r[0]), "=r"(r[1]), "=r"(r[2]), "=r"(r[3]) : "r"(addr));
}

// Taylor sin/cos for |t| <= ~1.3 (scan phase bounded by |Lam_im|*dt*delta).
// Truncation <= 3e-9. Validated in R13/R16: rel_err identical to sincosf.
static __device__ __forceinline__ float sin_poly(float t) {
    float t2 = t * t;
    float p = -2.5052108e-8f;
    p = fmaf(p, t2,  2.7557319e-6f);
    p = fmaf(p, t2, -1.9841270e-4f);
    p = fmaf(p, t2,  8.3333333e-3f);
    p = fmaf(p, t2, -0.16666667f);
    p = fmaf(p, t2,  1.0f);
    return t * p;
}
static __device__ __forceinline__ float cos_poly(float t) {
    float t2 = t * t;
    float p = 2.0876757e-9f;
    p = fmaf(p, t2, -2.7557319e-7f);
    p = fmaf(p, t2,  2.4801587e-5f);
    p = fmaf(p, t2, -1.3888889e-3f);
    p = fmaf(p, t2,  4.1666667e-2f);
    p = fmaf(p, t2, -0.5f);
    p = fmaf(p, t2,  1.0f);
    return p;
}

// ---------------- 3xTF32 mma.sync GEMM, 2 CTAs/SM ----------------------------
// C(128x128 per CTA) = A(M x K) @ Bt(N x K)^T
// 8 warps (2m x 4n), warp tile 64x32, BK=16, 2-stage cp.async pipeline.
// SMEM per stage: Ah | Al | Bh | Bl planes (128 rows x 20 floats each) = 40KB;
// 2 stages = 80KB/CTA -> 2 CTAs/SM. A-fragments use ONE register bank:
// per kk: ldsm al -> mma al*bh; reload ah into same regs -> mma ah*bl, ah*bh.
// Per-acc order stays small,small,big. Regs ~120 -> __launch_bounds__(256,2).
// Epilogue modes:
//  0: +bias, dual store to C and C2 (embed -> right_u/left_u)
//  1: plain store, row stride ldc (Bu)
//  2: gelu then split-store hi->C, lo->C2, stride 256
//  3: interleaved GLU pairs: C[r][gc/2] += (t1+b1)*sigmoid(t2+b2)
#define BKK   16
#define PADF  20                         // floats per smem row (80B, 16B-aligned)
#define PLANE (128*PADF)                 // one operand plane (floats)
#define STGF  (4*PLANE)                  // stage floats (Ah,Al,Bh,Bl)
#define GSMEM (2*STGF*4)                 // 81920 bytes

static __device__ __forceinline__ void load_stage(uint32_t sb, int s,
                                                  const float* Ah, const float* Al,
                                                  const float* Bh, const float* Bl,
                                                  int K, int kt, int tid) {
    uint32_t st = sb + (uint32_t)s * (STGF * 4);
    const float* srcs[4] = { Ah, Al, Bh, Bl };
#pragma unroll
    for (int pl = 0; pl < 4; pl++) {
        const float* src = srcs[pl];
        uint32_t base = st + pl * (PLANE * 4);
#pragma unroll
        for (int i = 0; i < 2; i++) {        // 128 rows x 4 float4 = 512 f4 / 256 thr
            int f = tid + i * 256;
            int row = f >> 2, ch = f & 3;
            cp16(base + row * (PADF * 4) + ch * 16, src + (size_t)row * K + kt + ch * 4);
        }
    }
}

__global__ __launch_bounds__(256, 2) void gemm_mma(
    const float* __restrict__ Ahi, const float* __restrict__ Alo,
    const float* __restrict__ Bhi, const float* __restrict__ Blo,
    const float* __restrict__ bias, float* __restrict__ C, float* __restrict__ C2,
    int ldc, int K, int mode)
{
    extern __shared__ float sm[];
    uint32_t sb = smem_u32(sm);
    int tid = threadIdx.x;
    int warp = tid >> 5, lane = tid & 31;
    int wm = warp & 1, wn = warp >> 1;
    int bx = blockIdx.x, by = blockIdx.y;

    const size_t aoff = (size_t)by * 128 * K;
    const size_t boff = (size_t)bx * 128 * K;
    const float* Ah = Ahi + aoff; const float* Al = Alo + aoff;
    const float* Bh = Bhi + boff; const float* Bl = Blo + boff;
    int NT = K / BKK;

    float acc[4][4][4];
#pragma unroll
    for (int mt = 0; mt < 4; mt++)
#pragma unroll
        for (int nt = 0; nt < 4; nt++)
#pragma unroll
            for (int e = 0; e < 4; e++) acc[mt][nt][e] = 0.f;

    load_stage(sb, 0, Ah, Al, Bh, Bl, K, 0, tid); CP_COMMIT();

    // ldmatrix lane address bases (byte offsets within a plane)
    int lj = lane >> 3, li = lane & 7;
    uint32_t aoff0 = (uint32_t)(((wm * 64 + (lj & 1) * 8 + li) * PADF + ((lj >> 1) << 2)) * 4);
    uint32_t boff0 = (uint32_t)(((wn * 32 + (lj >> 1) * 8 + li) * PADF + ((lj & 1) << 2)) * 4);

    for (int t = 0; t < NT; t++) {
        if (t + 1 < NT) {
            load_stage(sb, (t + 1) & 1, Ah, Al, Bh, Bl, K, (t + 1) * BKK, tid);
            CP_COMMIT(); CP_WAIT1();
        } else {
            CP_WAIT0();
        }
        __syncthreads();
        uint32_t S   = sb + (uint32_t)(t & 1) * (STGF * 4);
        uint32_t pAh = S;
        uint32_t pAl = S + PLANE * 4;
        uint32_t pBh = S + 2 * (PLANE * 4);
        uint32_t pBl = S + 3 * (PLANE * 4);
#pragma unroll
        for (int kk = 0; kk < 2; kk++) {
            uint32_t koff = kk * 32;              // 8 floats
            uint32_t a[4][4], bh[2][4], bl[2][4];
#pragma unroll
            for (int np = 0; np < 2; np++)
                ldsm4(bh[np], pBh + boff0 + np * (16 * PADF * 4) + koff);
#pragma unroll
            for (int np = 0; np < 2; np++)
                ldsm4(bl[np], pBl + boff0 + np * (16 * PADF * 4) + koff);
            // 1) al * bh  (small)
#pragma unroll
            for (int mt = 0; mt < 4; mt++)
                ldsm4(a[mt], pAl + aoff0 + mt * (16 * PADF * 4) + koff);
#pragma unroll
            for (int mt = 0; mt < 4; mt++)
#pragma unroll
                for (int nt = 0; nt < 4; nt++)
                    mma8(acc[mt][nt], a[mt], &bh[nt >> 1][2 * (nt & 1)]);
            // 2) ah * bl  (small)   -- reuse a-registers for ah
#pragma unroll
            for (int mt = 0; mt < 4; mt++)
                ldsm4(a[mt], pAh + aoff0 + mt * (16 * PADF * 4) + koff);
#pragma unroll
            for (int mt = 0; mt < 4; mt++)
#pragma unroll
                for (int nt = 0; nt < 4; nt++)
                    mma8(acc[mt][nt], a[mt], &bl[nt >> 1][2 * (nt & 1)]);
            // 3) ah * bh  (dominant last)
#pragma unroll
            for (int mt = 0; mt < 4; mt++)
#pragma unroll
                for (int nt = 0; nt < 4; nt++)
                    mma8(acc[mt][nt], a[mt], &bh[nt >> 1][2 * (nt & 1)]);
        }
        __syncthreads();
    }

    // ---------------- epilogue ----------------
    int rowb = by * 128 + wm * 64 + (lane >> 2);
    int colb = bx * 128 + wn * 32 + 2 * (lane & 3);
#pragma unroll
    for (int mt = 0; mt < 4; mt++) {
#pragma unroll
        for (int half = 0; half < 2; half++) {
            size_t r = (size_t)(rowb + mt * 16 + half * 8);
#pragma unroll
            for (int nt = 0; nt < 4; nt++) {
                float v0 = acc[mt][nt][half * 2 + 0];
                float v1 = acc[mt][nt][half * 2 + 1];
                int gc = colb + nt * 8;
                if (mode == 0) {
                    v0 += bias[gc]; v1 += bias[gc + 1];
                    float2 v = make_float2(v0, v1);
                    *(float2*)(C  + r * 256 + gc) = v;
                    *(float2*)(C2 + r * 256 + gc) = v;
                } else if (mode == 1) {
                    *(float2*)(C + r * (size_t)ldc + gc) = make_float2(v0, v1);
                } else if (mode == 2) {
                    float t0 = tanhf(0.79788456080286535588f * (v0 + 0.044715f * v0 * v0 * v0));
                    float t1 = tanhf(0.79788456080286535588f * (v1 + 0.044715f * v1 * v1 * v1));
                    float g0 = 0.5f * v0 * (1.f + t0);
                    float g1 = 0.5f * v1 * (1.f + t1);
                    float h0, l0, h1, l1;
                    fsplit(g0, h0, l0); fsplit(g1, h1, l1);
                    *(float2*)(C  + r * 256 + gc) = make_float2(h0, h1);
                    *(float2*)(C2 + r * 256 + gc) = make_float2(l0, l1);
                } else {
                    float t1 = v0 + bias[gc];
                    float t2 = v1 + bias[gc + 1];
                    C[r * 256 + (gc >> 1)] += t1 * (1.f / (1.f + expf(-t2)));
                }
            }
        }
    }
}

// ---------------- weight packing (transposed, K-major rows, hi/lo) -----------
__global__ void pack_kernel(const float* __restrict__ B_re, const float* __restrict__ B_im,
                            const float* __restrict__ C_re, const float* __restrict__ C_im,
                            const float* __restrict__ W1,   const float* __restrict__ W2,
                            const float* __restrict__ b1,   const float* __restrict__ b2,
                            const float* __restrict__ embW,
                            float* __restrict__ Wh, float* __restrict__ Wl)
{
    int idx = blockIdx.x * blockDim.x + threadIdx.x;
    int total = NLAYER * LSP + 65536;
    if (idx >= total) return;
    float val;
    bool is_bias = false;
    if (idx >= NLAYER * LSP) {               // embed^T: Et[n][k] = embW[k][n]
        int r = idx - NLAYER * LSP;
        int n = r >> 8, k = r & 255;
        val = embW[k * 256 + n];
    } else {
        int l = idx / LSP;
        int r = idx - l * LSP;
        if (r < 131072) {                    // Bt[j][h] = B_re/B_im[h][j]
            int j = r >> 8, h = r & 255;
            val = (j < 256) ? B_re[l * 65536 + h * 256 + j]
                            : B_im[l * 65536 + h * 256 + (j - 256)];
        } else if (r < 262144) {             // Ct[h][k] = C_re[k][h] / -C_im
            int r2 = r - 131072;
            int h = r2 >> 9, k = r2 & 511;
            val = (k < 256) ? C_re[l * 65536 + k * 256 + h]
                            : -C_im[l * 65536 + (k - 256) * 256 + h];
        } else if (r < 393216) {             // Wt[n][k], n even->W1 col n/2, odd->W2
            int r3 = r - 262144;
            int n = r3 >> 8, k = r3 & 255;
            val = (n & 1) ? W2[l * 65536 + k * 256 + (n >> 1)]
                          : W1[l * 65536 + k * 256 + (n >> 1)];
        } else {                             // interleaved bias (exact fp32)
            int n = r - 393216;
            val = (n & 1) ? b2[l * 256 + (n >> 1)] : b1[l * 256 + (n >> 1)];
            is_bias = true;
        }
    }
    if (is_bias) { Wh[idx] = val; Wl[idx] = 0.f; }
    else { float h, lo; fsplit(val, h, lo); Wh[idx] = h; Wl[idx] = lo; }
}

// ---------------- x_payload split --------------------------------------------
__global__ void split_kernel(const float* __restrict__ x,
                             float* __restrict__ hi, float* __restrict__ lo, int n)
{
    int i = blockIdx.x * blockDim.x + threadIdx.x;
    if (i < n) { float h, l; fsplit(x[i], h, l); hi[i] = h; lo[i] = l; }
}

// ---------------- LayerNorm (one warp per row of 256), split output ----------
__global__ void ln_kernel(const float* __restrict__ in, const float* __restrict__ scale,
                          const float* __restrict__ bias,
                          float* __restrict__ oh, float* __restrict__ ol, int rows)
{
    int warp = (blockIdx.x * blockDim.x + threadIdx.x) >> 5;
    int lane = threadIdx.x & 31;
    if (warp >= rows) return;
    const float* x = in + (size_t)warp * 256;
    float v[8], s = 0.f;
#pragma unroll
    for (int i = 0; i < 8; i++) { v[i] = x[lane + 32 * i]; s += v[i]; }
#pragma unroll
    for (int o = 16; o; o >>= 1) s += __shfl_xor_sync(0xffffffffu, s, o);
    float mn = s * (1.f / 256.f), q = 0.f;
#pragma unroll
    for (int i = 0; i < 8; i++) { float d = v[i] - mn; q += d * d; }
#pragma unroll
    for (int o = 16; o; o >>= 1) q += __shfl_xor_sync(0xffffffffu, q, o);
    float inv = rsqrtf(q * (1.f / 256.f) + 1e-5f);
#pragma unroll
    for (int i = 0; i < 8; i++) {
        int h = lane + 32 * i;
        float y = (v[i] - mn) * inv * scale[h] + bias[h];
        float yh, yl; fsplit(y, yh, yl);
        oh[(size_t)warp * 256 + h] = yh;
        ol[(size_t)warp * 256 + h] = yl;
    }
}

// ---------------- complex affine scan along N, split output ------------------
// grid (16 pg, 16 b), block 256 = 16 p-lanes x 16 chunks of 128 steps.
__global__ __launch_bounds__(256) void scan_kernel(
    const float* __restrict__ Bu, const float* __restrict__ dt,
    const float* __restrict__ Lre, const float* __restrict__ Lim,
    const float* __restrict__ logdelta,
    const float* __restrict__ ire, const float* __restrict__ iim,
    float* __restrict__ Xh, float* __restrict__ Xl)
{
    __shared__ float dts[SEQ];
    __shared__ float agg[16][16][4];
    __shared__ float carry[16][16][2];
    int b = blockIdx.y, pg = blockIdx.x;
    int tid = threadIdx.x;
    int pl = tid & 15, c = tid >> 4;
    int p = pg * 16 + pl;

    for (int i = tid; i < SEQ; i += 256) dts[i] = dt[b * SEQ + i];
    float nE = -expf(Lre[p]);
    float lim = Lim[p];
    float del = expf(logdelta[p]);
    __syncthreads();

    int n0 = c * 128;
    size_t rowbase = ((size_t)b * SEQ + n0) * 512 + p;
    const float* bup = Bu + rowbase;

    // phase 1: chunk aggregates with zero initial state
    float Ar = 1.f, Ai = 0.f, Xr = 0.f, Xi = 0.f;
    for (int j = 0; j < 128; j++) {
        float dte = dts[n0 + j] * del;
        float mag = expf(nE * dte);
        float th = lim * dte;
        float ar = mag * cos_poly(th), ai = mag * sin_poly(th);
        float br = bup[(size_t)j * 512], bi = bup[(size_t)j * 512 + 256];
        float nAr = Ar * ar - Ai * ai, nAi = Ar * ai + Ai * ar;
        float nXr = Xr * ar - Xi * ai + br, nXi = Xr * ai + Xi * ar + bi;
        Ar = nAr; Ai = nAi; Xr = nXr; Xi = nXi;
    }
    agg[c][pl][0] = Ar; agg[c][pl][1] = Ai; agg[c][pl][2] = Xr; agg[c][pl][3] = Xi;
    __syncthreads();

    // serial carry across 16 chunks (threads 0..15), x0 injection via init
    if (c == 0) {
        float cr = ire[p], ci = iim[p];
        carry[0][pl][0] = cr; carry[0][pl][1] = ci;
        for (int cc = 1; cc < 16; cc++) {
            float Aor = agg[cc-1][pl][0], Aoi = agg[cc-1][pl][1];
            float Xor_ = agg[cc-1][pl][2], Xoi = agg[cc-1][pl][3];
            float nr = Aor * cr - Aoi * ci + Xor_;
            float ni = Aor * ci + Aoi * cr + Xoi;
            cr = nr; ci = ni;
            carry[cc][pl][0] = cr; carry[cc][pl][1] = ci;
        }
    }
    __syncthreads();

    // phase 2: replay with true carry; emit x_left = a*x_prev, x_right = x_left + Bu
    float xr = carry[c][pl][0], xi = carry[c][pl][1];
    const size_t LHALF = (size_t)BNTOT * 512;
    for (int j = 0; j < 128; j++) {
        float dte = dts[n0 + j] * del;
        float mag = expf(nE * dte);
        float th = lim * dte;
        float ar = mag * cos_poly(th), ai = mag * sin_poly(th);
        float br = bup[(size_t)j * 512], bi = bup[(size_t)j * 512 + 256];
        float lr = ar * xr - ai * xi, li2 = ar * xi + ai * xr;   // left limit
        float rr = lr + br,           ri  = li2 + bi;            // right limit
        float h, l;
        size_t o = rowbase + (size_t)j * 512;
        fsplit(lr,  h, l); Xh[LHALF + o]       = h; Xl[LHALF + o]       = l;
        fsplit(li2, h, l); Xh[LHALF + o + 256] = h; Xl[LHALF + o + 256] = l;
        fsplit(rr,  h, l); Xh[o]               = h; Xl[o]               = l;
        fsplit(ri,  h, l); Xh[o + 256]         = h; Xl[o + 256]         = l;
        xr = rr; xi = ri;
    }
}

__global__ void out_kernel(const float* __restrict__ Uleft, float* __restrict__ out, int n)
{
    int i = blockIdx.x * blockDim.x + threadIdx.x;
    if (i < n) {
        int row = i >> 8;
        int nn = row & (SEQ - 1);
        out[i] = (nn == 0) ? 0.f : Uleft[i];
    }
}

// ---------------- driver -----------------------------------------------------
extern "C" void kernel_launch(void* const* d_in, const int* in_sizes, int n_in,
                              void* d_out, int out_size)
{
    (void)in_sizes; (void)n_in; (void)out_size;
    const float* x_payload = (const float*)d_in[0];
    const float* dt        = (const float*)d_in[1];
    const float* embed_W   = (const float*)d_in[2];
    const float* embed_b   = (const float*)d_in[3];
    const float* ln_scale  = (const float*)d_in[4];
    const float* ln_bias   = (const float*)d_in[5];
    const float* Lambda_re = (const float*)d_in[6];
    const float* Lambda_im = (const float*)d_in[7];
    const float* log_delta = (const float*)d_in[8];
    const float* B_re      = (const float*)d_in[9];
    const float* B_im      = (const float*)d_in[10];
    const float* C_re      = (const float*)d_in[11];
    const float* C_im      = (const float*)d_in[12];
    const float* W1        = (const float*)d_in[13];
    const float* b1        = (const float*)d_in[14];
    const float* W2        = (const float*)d_in[15];
    const float* b2        = (const float*)d_in[16];
    const float* init_re   = (const float*)d_in[17];
    const float* init_im   = (const float*)d_in[18];
    float* out = (float*)d_out;

    float *Vh, *Vl, *Bu, *Xh, *Xl, *Yh, *Yl, *U, *Wh, *Wl, *Ph, *Pl;
    cudaGetSymbolAddress((void**)&Vh, g_Vh);
    cudaGetSymbolAddress((void**)&Vl, g_Vl);
    cudaGetSymbolAddress((void**)&Bu, g_Bu);
    cudaGetSymbolAddress((void**)&Xh, g_Xh);
    cudaGetSymbolAddress((void**)&Xl, g_Xl);
    cudaGetSymbolAddress((void**)&Yh, g_Yh);
    cudaGetSymbolAddress((void**)&Yl, g_Yl);
    cudaGetSymbolAddress((void**)&U,  g_U);
    cudaGetSymbolAddress((void**)&Wh, g_Wh);
    cudaGetSymbolAddress((void**)&Wl, g_Wl);
    cudaGetSymbolAddress((void**)&Ph, g_Ph);
    cudaGetSymbolAddress((void**)&Pl, g_Pl);

    cudaFuncSetAttribute(gemm_mma, cudaFuncAttributeMaxDynamicSharedMemorySize, GSMEM);

    {
        int total = NLAYER * LSP + 65536;
        pack_kernel<<<(total + 255) / 256, 256>>>(B_re, B_im, C_re, C_im, W1, W2,
                                                  b1, b2, embed_W, Wh, Wl);
    }
    const int n1 = BNTOT * 256;
    split_kernel<<<(n1 + 255) / 256, 256>>>(x_payload, Ph, Pl, n1);

    float* EmbH = Wh + (size_t)NLAYER * LSP;
    float* EmbL = Wl + (size_t)NLAYER * LSP;
    float* U1   = U + (size_t)BNTOT * 256;

    // alpha = x @ embed_W + b -> right_u and left_u   (mode 0)
    gemm_mma<<<dim3(2, 256), 256, GSMEM>>>(Ph, Pl, EmbH, EmbL, embed_b, U, U1, 256, 256, 0);

    for (int l = 0; l < NLAYER; l++) {
        size_t wo = (size_t)l * LSP;
        ln_kernel<<<4096, 256>>>(U, ln_scale + l * 256, ln_bias + l * 256, Vh, Vl, BNTOT);
        // Bu = v @ [B_re|B_im]   (mode 1, out stride 512)
        gemm_mma<<<dim3(4, 256), 256, GSMEM>>>(Vh, Vl, Wh + wo, Wl + wo,
                                               nullptr, Bu, nullptr, 512, 256, 1);
        scan_kernel<<<dim3(16, 16), 256>>>(Bu, dt,
                                           Lambda_re + l * 256, Lambda_im + l * 256,
                                           log_delta + l * 256,
                                           init_re + l * 256, init_im + l * 256, Xh, Xl);
        // g = gelu(X @ [C_re;-C_im])   (mode 2, both streams stacked on M)
        gemm_mma<<<dim3(2, 512), 256, GSMEM>>>(Xh, Xl, Wh + wo + 131072, Wl + wo + 131072,
                                               nullptr, Yh, Yl, 256, 512, 2);
        // U += (g@W1+b1)*sigmoid(g@W2+b2)  (mode 3, interleaved columns)
        gemm_mma<<<dim3(4, 512), 256, GSMEM>>>(Yh, Yl, Wh + wo + 262144, Wl + wo + 262144,
                                               Wh + wo + 393216, U, nullptr, 256, 256, 3);
    }

    out_kernel<<<(n1 + 255) / 256, 256>>>(U1, out, n1);
}